// round 14
// baseline (speedup 1.0000x reference)
#include <cuda_runtime.h>
#include <cuda_fp16.h>
#include <math.h>
#include <stdint.h>

#define IN_DIM   256
#define OUT_DIM  64
#define NUM_HEADS 8
#define BATCH    8
#define SEQ      1024
#define QKV_COLS (OUT_DIM * NUM_HEADS)   // 512
#define ROWS     (BATCH * SEQ)           // 8192

// fp16 split tensors (Q pre-scaled by 0.125*log2(e)). K/V hi only.
__device__ __half g_Qh[ROWS * QKV_COLS];
__device__ __half g_Ql[ROWS * QKV_COLS];
__device__ __half g_Kh[ROWS * QKV_COLS];
__device__ __half g_Vh[ROWS * QKV_COLS];
__device__ float g_kmax[BATCH * NUM_HEADS];          // zero-init; atomicMax idempotent
__device__ unsigned long long g_adjbits[SEQ * 16];   // packed adjacency bits

#define QSCALE 0.18033688011112042f     // 0.125 * log2(e)

// ---------------------------------------------------------------------------
// helpers
// ---------------------------------------------------------------------------
__device__ __forceinline__ uint32_t smem_u32(const void* p) {
    uint32_t a;
    asm("{ .reg .u64 t; cvta.to.shared.u64 t, %1; cvt.u32.u64 %0, t; }"
        : "=r"(a) : "l"(p));
    return a;
}
__device__ __forceinline__ float ex2(float x) {
    float r;
    asm("ex2.approx.f32 %0, %1;" : "=f"(r) : "f"(x));
    return r;
}
__device__ __forceinline__ uint32_t pack_hf2(float a, float b) {
    __half2 t = __floats2half2_rn(a, b);
    return *reinterpret_cast<uint32_t*>(&t);
}
__device__ __forceinline__ float2 hf2f(uint32_t u) {
    __half2 h = *reinterpret_cast<__half2*>(&u);
    return __half22float2(h);
}
__device__ __forceinline__ void split2(float a, float b, uint32_t& hi, uint32_t& lo) {
    float ah = __half2float(__float2half_rn(a));
    float bh = __half2float(__float2half_rn(b));
    hi = pack_hf2(ah, bh);
    lo = pack_hf2(a - ah, b - bh);
}
__device__ __forceinline__ void ldsm_x4(uint32_t* r, uint32_t addr) {
    asm volatile("ldmatrix.sync.aligned.m8n8.x4.shared.b16 {%0,%1,%2,%3}, [%4];"
        : "=r"(r[0]), "=r"(r[1]), "=r"(r[2]), "=r"(r[3]) : "r"(addr));
}
__device__ __forceinline__ void ldsm_x4_t(uint32_t* r, uint32_t addr) {
    asm volatile("ldmatrix.sync.aligned.m8n8.x4.trans.shared.b16 {%0,%1,%2,%3}, [%4];"
        : "=r"(r[0]), "=r"(r[1]), "=r"(r[2]), "=r"(r[3]) : "r"(addr));
}
__device__ __forceinline__ void mma16816(float* d, const uint32_t* a,
                                         uint32_t b0, uint32_t b1) {
    asm volatile("mma.sync.aligned.m16n8k16.row.col.f32.f16.f16.f32 "
        "{%0,%1,%2,%3}, {%4,%5,%6,%7}, {%8,%9}, {%0,%1,%2,%3};"
        : "+f"(d[0]), "+f"(d[1]), "+f"(d[2]), "+f"(d[3])
        : "r"(a[0]), "r"(a[1]), "r"(a[2]), "r"(a[3]), "r"(b0), "r"(b1));
}
__device__ __forceinline__ void cp16(uint32_t dst, const void* src) {
    asm volatile("cp.async.cg.shared.global [%0], [%1], 16;"
                 :: "r"(dst), "l"(src) : "memory");
}
#define CP_COMMIT() asm volatile("cp.async.commit_group;" ::: "memory")
#define CP_WAIT0()  asm volatile("cp.async.wait_group 0;" ::: "memory")

// ---------------------------------------------------------------------------
// Kernel 1: QKV projection via mma.sync fp16 (3-pass for Q/K, 2-pass for V);
// W split in-kernel.  z==3 slice packs the adjacency bits (ballot).
// (unchanged from R13)
// ---------------------------------------------------------------------------
#define QA_STR 40
#define QB_STR 136

__global__ __launch_bounds__(256, 2)
void qkv_mma_kernel(const float* __restrict__ h,
                    const float* __restrict__ Wq,
                    const float* __restrict__ Wk,
                    const float* __restrict__ Wv,
                    const float* __restrict__ bq,
                    const float* __restrict__ bk,
                    const float* __restrict__ bv,
                    const int* __restrict__ adj)
{
    // ---- z==3: pack adjacency bits, one ballot per 32 ints ----
    if (blockIdx.z == 3) {
        int cta = blockIdx.y * 4 + blockIdx.x;          // 0..255
        int gw = cta * 8 + (threadIdx.x >> 5);          // global warp 0..2047
        int lane = threadIdx.x & 31;
        uint32_t* dst = (uint32_t*)g_adjbits;           // 32768 words
        const int* src = adj + (size_t)gw * 512;        // 16 ballots x 32 ints
        #pragma unroll
        for (int i = 0; i < 16; i++) {
            unsigned m = __ballot_sync(0xffffffffu, src[i * 32 + lane] != 0);
            if (lane == 0) dst[gw * 16 + i] = m;
        }
        return;
    }

    __shared__ __half sAh[128 * QA_STR];
    __shared__ __half sAl[128 * QA_STR];
    __shared__ __half sBh[32 * QB_STR];
    __shared__ __half sBl[32 * QB_STR];

    const int which = blockIdx.z;
    const float* __restrict__ W    = (which == 0) ? Wq : (which == 1) ? Wk : Wv;
    const float* __restrict__ bias = (which == 0) ? bq : (which == 1) ? bk : bv;
    __half* __restrict__ Oh = (which == 0) ? g_Qh : (which == 1) ? g_Kh : g_Vh;
    const float sc = (which == 0) ? QSCALE : 1.0f;
    const bool wlo_pass = (which != 2);    // V: 2-pass (h * W_hi exactly)

    const int tid  = threadIdx.x;
    const int w    = tid >> 5;
    const int lane = tid & 31;
    const int warp_m = w >> 1;
    const int warp_n = w & 1;
    const int g  = lane >> 2;
    const int t4 = lane & 3;
    const int row0 = blockIdx.y * 128;
    const int col0 = blockIdx.x * 128;

    const uint32_t aBaseH = smem_u32(sAh);
    const uint32_t aBaseL = smem_u32(sAl);
    const uint32_t bBaseH = smem_u32(sBh);
    const uint32_t bBaseL = smem_u32(sBl);

    float acc[2][8][4] = {};

    for (int kt = 0; kt < IN_DIM / 32; kt++) {
        const int k0 = kt * 32;
        #pragma unroll
        for (int it = 0; it < 2; it++) {
            int lin = it * 256 + tid;
            int r  = lin >> 2;
            int c8 = (lin & 3) * 8;
            const float* src = &h[(size_t)(row0 + r) * IN_DIM + k0 + c8];
            float4 v0 = *(const float4*)src;
            float4 v1 = *(const float4*)(src + 4);
            uint4 hi, lo;
            split2(v0.x, v0.y, hi.x, lo.x);
            split2(v0.z, v0.w, hi.y, lo.y);
            split2(v1.x, v1.y, hi.z, lo.z);
            split2(v1.z, v1.w, hi.w, lo.w);
            *(uint4*)&sAh[r * QA_STR + c8] = hi;
            *(uint4*)&sAl[r * QA_STR + c8] = lo;
        }
        #pragma unroll
        for (int it = 0; it < 4; it++) {
            int lin = it * 256 + tid;
            int r  = lin >> 5;
            int c4 = (lin & 31) * 4;
            float4 v = *(const float4*)&W[(size_t)(k0 + r) * QKV_COLS + col0 + c4];
            uint2 hi, lo;
            split2(v.x, v.y, hi.x, lo.x);
            split2(v.z, v.w, hi.y, lo.y);
            *(uint2*)&sBh[r * QB_STR + c4] = hi;
            *(uint2*)&sBl[r * QB_STR + c4] = lo;
        }
        __syncthreads();

        uint32_t ah[2][2][4], al[2][2][4];
        const int arow = (lane & 7) + 8 * ((lane >> 3) & 1);
        const int acol = 8 * (lane >> 4);
        #pragma unroll
        for (int mi = 0; mi < 2; mi++)
            #pragma unroll
            for (int kk = 0; kk < 2; kk++) {
                uint32_t off = (uint32_t)((32 * warp_m + 16 * mi + arow) * QA_STR
                                          + 16 * kk + acol) * 2;
                ldsm_x4(ah[mi][kk], aBaseH + off);
                ldsm_x4(al[mi][kk], aBaseL + off);
            }

        const int brow = (lane & 7) + 8 * (lane >> 3);
        #pragma unroll
        for (int nj = 0; nj < 8; nj++) {
            uint32_t bh4[4], bl4[4];
            uint32_t off = (uint32_t)(brow * QB_STR + 64 * warp_n + 8 * nj) * 2;
            ldsm_x4_t(bh4, bBaseH + off);
            ldsm_x4_t(bl4, bBaseL + off);
            #pragma unroll
            for (int mi = 0; mi < 2; mi++)
                #pragma unroll
                for (int kk = 0; kk < 2; kk++) {
                    mma16816(acc[mi][nj], ah[mi][kk], bh4[2 * kk], bh4[2 * kk + 1]);
                    mma16816(acc[mi][nj], al[mi][kk], bh4[2 * kk], bh4[2 * kk + 1]);
                    if (wlo_pass)
                        mma16816(acc[mi][nj], ah[mi][kk], bl4[2 * kk], bl4[2 * kk + 1]);
                }
        }
        __syncthreads();
    }

    float ssA[2] = {0.f, 0.f}, ssB[2] = {0.f, 0.f};
    #pragma unroll
    for (int nj = 0; nj < 8; nj++) {
        const int cc = col0 + 64 * warp_n + 8 * nj + 2 * t4;
        float2 bb = *(const float2*)&bias[cc];
        #pragma unroll
        for (int mi = 0; mi < 2; mi++) {
            const int r0 = row0 + 32 * warp_m + 16 * mi + g;
            float v0 = (acc[mi][nj][0] + bb.x) * sc;
            float v1 = (acc[mi][nj][1] + bb.y) * sc;
            float v2 = (acc[mi][nj][2] + bb.x) * sc;
            float v3 = (acc[mi][nj][3] + bb.y) * sc;
            ssA[mi] = fmaf(v0, v0, ssA[mi]); ssA[mi] = fmaf(v1, v1, ssA[mi]);
            ssB[mi] = fmaf(v2, v2, ssB[mi]); ssB[mi] = fmaf(v3, v3, ssB[mi]);
            uint32_t hi0, lo0, hi1, lo1;
            split2(v0, v1, hi0, lo0);
            split2(v2, v3, hi1, lo1);
            *(uint32_t*)&Oh[(size_t)r0 * QKV_COLS + cc]       = hi0;
            *(uint32_t*)&Oh[(size_t)(r0 + 8) * QKV_COLS + cc] = hi1;
            if (which == 0) {
                *(uint32_t*)&g_Ql[(size_t)r0 * QKV_COLS + cc]       = lo0;
                *(uint32_t*)&g_Ql[(size_t)(r0 + 8) * QKV_COLS + cc] = lo1;
            }
        }
    }

    if (which == 1) {
        float s0 = ssA[0], s1 = ssB[0], s2 = ssA[1], s3 = ssB[1];
        #pragma unroll
        for (int off = 1; off <= 2; off <<= 1) {
            s0 += __shfl_xor_sync(0xffffffffu, s0, off);
            s1 += __shfl_xor_sync(0xffffffffu, s1, off);
            s2 += __shfl_xor_sync(0xffffffffu, s2, off);
            s3 += __shfl_xor_sync(0xffffffffu, s3, off);
        }
        float mx = fmaxf(fmaxf(s0, s1), fmaxf(s2, s3));
        #pragma unroll
        for (int off = 4; off <= 16; off <<= 1)
            mx = fmaxf(mx, __shfl_xor_sync(0xffffffffu, mx, off));
        if (lane == 0) {
            int bh = (row0 >> 10) * NUM_HEADS + ((col0 + 64 * warp_n) >> 6);
            atomicMax((unsigned int*)&g_kmax[bh], __float_as_uint(mx));
        }
    }
}

// ---------------------------------------------------------------------------
// Kernel 2: fp16 2-pass flash attention.  BR=64, 4 warps, 3 CTAs/SM,
// cp.async double-buffered K/V, packed adjacency, interleaved MMA chains.
// ---------------------------------------------------------------------------
#define TSTR 72
#define KTILE_E (64 * TSTR)

__global__ __launch_bounds__(128, 3)
void attn_mma_kernel(float* __restrict__ out)
{
    extern __shared__ __half sm[];
    __half* sQh = sm;                    // [64][TSTR]
    __half* sQl = sQh + KTILE_E;
    __half* sK0 = sQl + KTILE_E;         // K/V double buffers
    __half* sK1 = sK0 + KTILE_E;
    __half* sV0 = sK1 + KTILE_E;
    __half* sV1 = sV0 + KTILE_E;
    float* sM = (float*)(sV1 + KTILE_E); // [64]

    const int b  = blockIdx.z;
    const int hd = blockIdx.y;
    const int q0 = blockIdx.x * 64;
    const int tid  = threadIdx.x;
    const int w    = tid >> 5;
    const int lane = tid & 31;
    const int g  = lane >> 2;
    const int t4 = lane & 3;

    const size_t bN  = (size_t)b * SEQ;
    const int hdo = hd * OUT_DIM;

    const uint32_t kbase[2] = { smem_u32(sK0), smem_u32(sK1) };
    const uint32_t vbase[2] = { smem_u32(sV0), smem_u32(sV1) };

    auto stage_kv = [&](int t, int buf) {
        const int m0 = t * 64;
        #pragma unroll
        for (int it = 0; it < 4; it++) {
            int lin = it * 128 + tid;
            int r  = lin >> 3;
            int c8 = (lin & 7) * 8;
            size_t gofs = (bN + m0 + r) * QKV_COLS + hdo + c8;
            uint32_t so = (uint32_t)(r * TSTR + c8) * 2;
            cp16(kbase[buf] + so, &g_Kh[gofs]);
            cp16(vbase[buf] + so, &g_Vh[gofs]);
        }
        CP_COMMIT();
    };

    #pragma unroll
    for (int it = 0; it < 4; it++) {
        int lin = it * 128 + tid;
        int r  = lin >> 3;
        int c8 = (lin & 7) * 8;
        *(uint4*)&sQh[r * TSTR + c8] =
            *(const uint4*)&g_Qh[(bN + q0 + r) * QKV_COLS + hdo + c8];
        *(uint4*)&sQl[r * TSTR + c8] =
            *(const uint4*)&g_Ql[(bN + q0 + r) * QKV_COLS + hdo + c8];
    }
    stage_kv(0, 0);
    __syncthreads();

    const float kmax2 = g_kmax[b * NUM_HEADS + hd];
    if (tid < 64) {
        float ss = 0.f;
        #pragma unroll
        for (int c = 0; c < 8; c++) {
            uint4 uh = *(const uint4*)&sQh[tid * TSTR + c * 8];
            uint4 ul = *(const uint4*)&sQl[tid * TSTR + c * 8];
            const uint32_t* ph = (const uint32_t*)&uh;
            const uint32_t* pl = (const uint32_t*)&ul;
            #pragma unroll
            for (int q = 0; q < 4; q++) {
                float2 fh = hf2f(ph[q]), fl = hf2f(pl[q]);
                float a = fh.x + fl.x, c2 = fh.y + fl.y;
                ss = fmaf(a, a, ss); ss = fmaf(c2, c2, ss);
            }
        }
        sM[tid] = sqrtf(ss * kmax2);
    }
    __syncthreads();

    const uint32_t qbase_h = smem_u32(sQh);
    const uint32_t qbase_l = smem_u32(sQl);
    uint32_t qh[4][4], ql[4][4];
    {
        int row = 16 * w + (lane & 7) + 8 * ((lane >> 3) & 1);
        int dof = 8 * (lane >> 4);
        #pragma unroll
        for (int kt = 0; kt < 4; kt++) {
            uint32_t off = (uint32_t)(row * TSTR + 16 * kt + dof) * 2;
            ldsm_x4(qh[kt], qbase_h + off);
            ldsm_x4(ql[kt], qbase_l + off);
        }
    }
    const float mg = sM[16 * w + g];
    const float m2 = sM[16 * w + g + 8];

    const int r1 = q0 + 16 * w + g;
    const unsigned long long* abits0 = &g_adjbits[(size_t)r1 * 16];
    const unsigned long long* abits1 = &g_adjbits[(size_t)(r1 + 8) * 16];

    float o[8][4] = {};
    float lg = 0.f, l2 = 0.f;

    for (int t = 0; t < SEQ / 64; t++) {
        const unsigned long long m0s = abits0[t] >> (2 * t4);
        const unsigned long long m1s = abits1[t] >> (2 * t4);

        CP_WAIT0();
        __syncthreads();
        if (t < SEQ / 64 - 1) stage_kv(t + 1, (t + 1) & 1);

        const uint32_t kb = kbase[t & 1];
        const uint32_t vb = vbase[t & 1];

        // ---- QK^T + mask + exp + split; two interleaved accumulator chains ----
        uint32_t ph[4][4], pl[4][4];
        const int krow = (lane & 7);
        const int kdof = 8 * (lane >> 3);
        #pragma unroll
        for (int kt = 0; kt < 4; kt++) {
            uint32_t b0[8], b1[8];
            uint32_t roff0 = (uint32_t)((16 * kt + krow) * TSTR + kdof) * 2;
            uint32_t roff1 = (uint32_t)((16 * kt + 8 + krow) * TSTR + kdof) * 2;
            ldsm_x4(b0 + 0, kb + roff0);
            ldsm_x4(b0 + 4, kb + roff0 + 64);
            ldsm_x4(b1 + 0, kb + roff1);
            ldsm_x4(b1 + 4, kb + roff1 + 64);
            float d0[4] = {}, d1[4] = {};
            #pragma unroll
            for (int kc = 0; kc < 4; kc++) {
                int hi2 = kc >> 1, oo = (kc & 1) * 2;
                mma16816(d0, qh[kc], b0[4 * hi2 + oo], b0[4 * hi2 + oo + 1]);
                mma16816(d1, qh[kc], b1[4 * hi2 + oo], b1[4 * hi2 + oo + 1]);
            }
            #pragma unroll
            for (int kc = 0; kc < 4; kc++) {
                int hi2 = kc >> 1, oo = (kc & 1) * 2;
                mma16816(d0, ql[kc], b0[4 * hi2 + oo], b0[4 * hi2 + oo + 1]);
                mma16816(d1, ql[kc], b1[4 * hi2 + oo], b1[4 * hi2 + oo + 1]);
            }
            unsigned b00 = (unsigned)(m0s >> (16 * kt)) & 3u;
            unsigned b01 = (unsigned)(m1s >> (16 * kt)) & 3u;
            unsigned b10 = (unsigned)(m0s >> (16 * kt + 8)) & 3u;
            unsigned b11 = (unsigned)(m1s >> (16 * kt + 8)) & 3u;
            float p00 = (b00 & 1) ? ex2(d0[0] - mg) : 0.f;
            float p01 = (b00 & 2) ? ex2(d0[1] - mg) : 0.f;
            float p02 = (b01 & 1) ? ex2(d0[2] - m2) : 0.f;
            float p03 = (b01 & 2) ? ex2(d0[3] - m2) : 0.f;
            float p10 = (b10 & 1) ? ex2(d1[0] - mg) : 0.f;
            float p11 = (b10 & 2) ? ex2(d1[1] - mg) : 0.f;
            float p12 = (b11 & 1) ? ex2(d1[2] - m2) : 0.f;
            float p13 = (b11 & 2) ? ex2(d1[3] - m2) : 0.f;
            lg += (p00 + p01) + (p10 + p11);
            l2 += (p02 + p03) + (p12 + p13);
            split2(p00, p01, ph[kt][0], pl[kt][0]);
            split2(p02, p03, ph[kt][1], pl[kt][1]);
            split2(p10, p11, ph[kt][2], pl[kt][2]);
            split2(p12, p13, ph[kt][3], pl[kt][3]);
        }

        // ---- PV: j-pairs, two interleaved accumulator chains ----
        const int vrow = 8 * (lane >> 3) + (lane & 7);
        const uint32_t vr0  = (uint32_t)(vrow * TSTR) * 2;
        const uint32_t vr32 = (uint32_t)((vrow + 32) * TSTR) * 2;
        #pragma unroll
        for (int jp = 0; jp < 4; jp++) {
            const int j0 = 2 * jp, j1 = j0 + 1;
            uint32_t b0[8], b1[8];
            uint32_t c0 = (uint32_t)(8 * j0) * 2;
            uint32_t c1 = (uint32_t)(8 * j1) * 2;
            ldsm_x4_t(b0 + 0, vb + vr0 + c0);
            ldsm_x4_t(b0 + 4, vb + vr32 + c0);
            ldsm_x4_t(b1 + 0, vb + vr0 + c1);
            ldsm_x4_t(b1 + 4, vb + vr32 + c1);
            #pragma unroll
            for (int kt = 0; kt < 4; kt++) {
                int hi2 = kt >> 1, oo = (kt & 1) * 2;
                uint32_t v00 = b0[4 * hi2 + oo], v01 = b0[4 * hi2 + oo + 1];
                uint32_t v10 = b1[4 * hi2 + oo], v11 = b1[4 * hi2 + oo + 1];
                mma16816(o[j0], ph[kt], v00, v01);
                mma16816(o[j1], ph[kt], v10, v11);
                mma16816(o[j0], pl[kt], v00, v01);
                mma16816(o[j1], pl[kt], v10, v11);
            }
        }
    }

    lg += __shfl_xor_sync(0xffffffffu, lg, 1);
    lg += __shfl_xor_sync(0xffffffffu, lg, 2);
    l2 += __shfl_xor_sync(0xffffffffu, l2, 1);
    l2 += __shfl_xor_sync(0xffffffffu, l2, 2);
    const float invg = 1.0f / lg;
    const float inv2 = 1.0f / l2;

    #pragma unroll
    for (int j = 0; j < 8; j++) {
        int cc = hdo + 8 * j + 2 * t4;
        *(float2*)&out[(bN + r1) * QKV_COLS + cc] =
            make_float2(o[j][0] * invg, o[j][1] * invg);
        *(float2*)&out[(bN + r1 + 8) * QKV_COLS + cc] =
            make_float2(o[j][2] * inv2, o[j][3] * inv2);
    }
}

// ---------------------------------------------------------------------------
// Launch
// ---------------------------------------------------------------------------
extern "C" void kernel_launch(void* const* d_in, const int* in_sizes, int n_in,
                              void* d_out, int out_size)
{
    const int*   adj = (const int*)  d_in[0];
    const float* h   = (const float*)d_in[1];
    const float* Wq  = (const float*)d_in[2];
    const float* bq  = (const float*)d_in[3];
    const float* Wk  = (const float*)d_in[4];
    const float* bk  = (const float*)d_in[5];
    const float* Wv  = (const float*)d_in[6];
    const float* bv  = (const float*)d_in[7];
    float* out = (float*)d_out;

    qkv_mma_kernel<<<dim3(QKV_COLS / 128, ROWS / 128, 4), 256>>>(
        h, Wq, Wk, Wv, bq, bk, bv, adj);

    const int smem_bytes = 6 * KTILE_E * 2 + 64 * 4;   // 55,552 B
    static bool attr_set = false;
    if (!attr_set) {
        cudaFuncSetAttribute(attn_mma_kernel,
                             cudaFuncAttributeMaxDynamicSharedMemorySize, smem_bytes);
        attr_set = true;
    }
    attn_mma_kernel<<<dim3(SEQ / 64, NUM_HEADS, BATCH), 128, smem_bytes>>>(out);
}

// round 15
// speedup vs baseline: 1.1047x; 1.1047x over previous
#include <cuda_runtime.h>
#include <cuda_fp16.h>
#include <math.h>
#include <stdint.h>

#define IN_DIM   256
#define OUT_DIM  64
#define NUM_HEADS 8
#define BATCH    8
#define SEQ      1024
#define QKV_COLS (OUT_DIM * NUM_HEADS)   // 512
#define ROWS     (BATCH * SEQ)           // 8192

// fp16 split tensors (Q pre-scaled by 0.125*log2(e)). K/V hi only.
__device__ __half g_Qh[ROWS * QKV_COLS];
__device__ __half g_Ql[ROWS * QKV_COLS];
__device__ __half g_Kh[ROWS * QKV_COLS];
__device__ __half g_Vh[ROWS * QKV_COLS];
__device__ float g_kmax[BATCH * NUM_HEADS];          // zero-init; atomicMax idempotent
__device__ unsigned long long g_adjbits[SEQ * 16];   // packed adjacency bits

#define QSCALE 0.18033688011112042f     // 0.125 * log2(e)

// ---------------------------------------------------------------------------
// helpers
// ---------------------------------------------------------------------------
__device__ __forceinline__ uint32_t smem_u32(const void* p) {
    uint32_t a;
    asm("{ .reg .u64 t; cvta.to.shared.u64 t, %1; cvt.u32.u64 %0, t; }"
        : "=r"(a) : "l"(p));
    return a;
}
__device__ __forceinline__ float ex2(float x) {
    float r;
    asm("ex2.approx.f32 %0, %1;" : "=f"(r) : "f"(x));
    return r;
}
__device__ __forceinline__ uint32_t pack_hf2(float a, float b) {
    __half2 t = __floats2half2_rn(a, b);
    return *reinterpret_cast<uint32_t*>(&t);
}
__device__ __forceinline__ float2 hf2f(uint32_t u) {
    __half2 h = *reinterpret_cast<__half2*>(&u);
    return __half22float2(h);
}
__device__ __forceinline__ void split2(float a, float b, uint32_t& hi, uint32_t& lo) {
    float ah = __half2float(__float2half_rn(a));
    float bh = __half2float(__float2half_rn(b));
    hi = pack_hf2(ah, bh);
    lo = pack_hf2(a - ah, b - bh);
}
__device__ __forceinline__ void ldsm_x4(uint32_t* r, uint32_t addr) {
    asm volatile("ldmatrix.sync.aligned.m8n8.x4.shared.b16 {%0,%1,%2,%3}, [%4];"
        : "=r"(r[0]), "=r"(r[1]), "=r"(r[2]), "=r"(r[3]) : "r"(addr));
}
__device__ __forceinline__ void ldsm_x4_t(uint32_t* r, uint32_t addr) {
    asm volatile("ldmatrix.sync.aligned.m8n8.x4.trans.shared.b16 {%0,%1,%2,%3}, [%4];"
        : "=r"(r[0]), "=r"(r[1]), "=r"(r[2]), "=r"(r[3]) : "r"(addr));
}
__device__ __forceinline__ void mma16816(float* d, const uint32_t* a,
                                         uint32_t b0, uint32_t b1) {
    asm volatile("mma.sync.aligned.m16n8k16.row.col.f32.f16.f16.f32 "
        "{%0,%1,%2,%3}, {%4,%5,%6,%7}, {%8,%9}, {%0,%1,%2,%3};"
        : "+f"(d[0]), "+f"(d[1]), "+f"(d[2]), "+f"(d[3])
        : "r"(a[0]), "r"(a[1]), "r"(a[2]), "r"(a[3]), "r"(b0), "r"(b1));
}
__device__ __forceinline__ void cp16(uint32_t dst, const void* src) {
    asm volatile("cp.async.cg.shared.global [%0], [%1], 16;"
                 :: "r"(dst), "l"(src) : "memory");
}
#define CP_COMMIT() asm volatile("cp.async.commit_group;" ::: "memory")
#define CP_WAIT0()  asm volatile("cp.async.wait_group 0;" ::: "memory")

// ---------------------------------------------------------------------------
// Kernel 1: QKV projection via mma.sync fp16 (3-pass for Q/K, 2-pass for V);
// W split in-kernel.  z==3 slice packs the adjacency bits (ballot).
// (unchanged from R13)
// ---------------------------------------------------------------------------
#define QA_STR 40
#define QB_STR 136

__global__ __launch_bounds__(256, 2)
void qkv_mma_kernel(const float* __restrict__ h,
                    const float* __restrict__ Wq,
                    const float* __restrict__ Wk,
                    const float* __restrict__ Wv,
                    const float* __restrict__ bq,
                    const float* __restrict__ bk,
                    const float* __restrict__ bv,
                    const int* __restrict__ adj)
{
    // ---- z==3: pack adjacency bits, one ballot per 32 ints ----
    if (blockIdx.z == 3) {
        int cta = blockIdx.y * 4 + blockIdx.x;          // 0..255
        int gw = cta * 8 + (threadIdx.x >> 5);          // global warp 0..2047
        int lane = threadIdx.x & 31;
        uint32_t* dst = (uint32_t*)g_adjbits;           // 32768 words
        const int* src = adj + (size_t)gw * 512;        // 16 ballots x 32 ints
        #pragma unroll
        for (int i = 0; i < 16; i++) {
            unsigned m = __ballot_sync(0xffffffffu, src[i * 32 + lane] != 0);
            if (lane == 0) dst[gw * 16 + i] = m;
        }
        return;
    }

    __shared__ __half sAh[128 * QA_STR];
    __shared__ __half sAl[128 * QA_STR];
    __shared__ __half sBh[32 * QB_STR];
    __shared__ __half sBl[32 * QB_STR];

    const int which = blockIdx.z;
    const float* __restrict__ W    = (which == 0) ? Wq : (which == 1) ? Wk : Wv;
    const float* __restrict__ bias = (which == 0) ? bq : (which == 1) ? bk : bv;
    __half* __restrict__ Oh = (which == 0) ? g_Qh : (which == 1) ? g_Kh : g_Vh;
    const float sc = (which == 0) ? QSCALE : 1.0f;
    const bool wlo_pass = (which != 2);    // V: 2-pass (h * W_hi exactly)

    const int tid  = threadIdx.x;
    const int w    = tid >> 5;
    const int lane = tid & 31;
    const int warp_m = w >> 1;
    const int warp_n = w & 1;
    const int g  = lane >> 2;
    const int t4 = lane & 3;
    const int row0 = blockIdx.y * 128;
    const int col0 = blockIdx.x * 128;

    const uint32_t aBaseH = smem_u32(sAh);
    const uint32_t aBaseL = smem_u32(sAl);
    const uint32_t bBaseH = smem_u32(sBh);
    const uint32_t bBaseL = smem_u32(sBl);

    float acc[2][8][4] = {};

    for (int kt = 0; kt < IN_DIM / 32; kt++) {
        const int k0 = kt * 32;
        #pragma unroll
        for (int it = 0; it < 2; it++) {
            int lin = it * 256 + tid;
            int r  = lin >> 2;
            int c8 = (lin & 3) * 8;
            const float* src = &h[(size_t)(row0 + r) * IN_DIM + k0 + c8];
            float4 v0 = *(const float4*)src;
            float4 v1 = *(const float4*)(src + 4);
            uint4 hi, lo;
            split2(v0.x, v0.y, hi.x, lo.x);
            split2(v0.z, v0.w, hi.y, lo.y);
            split2(v1.x, v1.y, hi.z, lo.z);
            split2(v1.z, v1.w, hi.w, lo.w);
            *(uint4*)&sAh[r * QA_STR + c8] = hi;
            *(uint4*)&sAl[r * QA_STR + c8] = lo;
        }
        #pragma unroll
        for (int it = 0; it < 4; it++) {
            int lin = it * 256 + tid;
            int r  = lin >> 5;
            int c4 = (lin & 31) * 4;
            float4 v = *(const float4*)&W[(size_t)(k0 + r) * QKV_COLS + col0 + c4];
            uint2 hi, lo;
            split2(v.x, v.y, hi.x, lo.x);
            split2(v.z, v.w, hi.y, lo.y);
            *(uint2*)&sBh[r * QB_STR + c4] = hi;
            *(uint2*)&sBl[r * QB_STR + c4] = lo;
        }
        __syncthreads();

        uint32_t ah[2][2][4], al[2][2][4];
        const int arow = (lane & 7) + 8 * ((lane >> 3) & 1);
        const int acol = 8 * (lane >> 4);
        #pragma unroll
        for (int mi = 0; mi < 2; mi++)
            #pragma unroll
            for (int kk = 0; kk < 2; kk++) {
                uint32_t off = (uint32_t)((32 * warp_m + 16 * mi + arow) * QA_STR
                                          + 16 * kk + acol) * 2;
                ldsm_x4(ah[mi][kk], aBaseH + off);
                ldsm_x4(al[mi][kk], aBaseL + off);
            }

        const int brow = (lane & 7) + 8 * (lane >> 3);
        #pragma unroll
        for (int nj = 0; nj < 8; nj++) {
            uint32_t bh4[4], bl4[4];
            uint32_t off = (uint32_t)(brow * QB_STR + 64 * warp_n + 8 * nj) * 2;
            ldsm_x4_t(bh4, bBaseH + off);
            ldsm_x4_t(bl4, bBaseL + off);
            #pragma unroll
            for (int mi = 0; mi < 2; mi++)
                #pragma unroll
                for (int kk = 0; kk < 2; kk++) {
                    mma16816(acc[mi][nj], ah[mi][kk], bh4[2 * kk], bh4[2 * kk + 1]);
                    mma16816(acc[mi][nj], al[mi][kk], bh4[2 * kk], bh4[2 * kk + 1]);
                    if (wlo_pass)
                        mma16816(acc[mi][nj], ah[mi][kk], bl4[2 * kk], bl4[2 * kk + 1]);
                }
        }
        __syncthreads();
    }

    float ssA[2] = {0.f, 0.f}, ssB[2] = {0.f, 0.f};
    #pragma unroll
    for (int nj = 0; nj < 8; nj++) {
        const int cc = col0 + 64 * warp_n + 8 * nj + 2 * t4;
        float2 bb = *(const float2*)&bias[cc];
        #pragma unroll
        for (int mi = 0; mi < 2; mi++) {
            const int r0 = row0 + 32 * warp_m + 16 * mi + g;
            float v0 = (acc[mi][nj][0] + bb.x) * sc;
            float v1 = (acc[mi][nj][1] + bb.y) * sc;
            float v2 = (acc[mi][nj][2] + bb.x) * sc;
            float v3 = (acc[mi][nj][3] + bb.y) * sc;
            ssA[mi] = fmaf(v0, v0, ssA[mi]); ssA[mi] = fmaf(v1, v1, ssA[mi]);
            ssB[mi] = fmaf(v2, v2, ssB[mi]); ssB[mi] = fmaf(v3, v3, ssB[mi]);
            uint32_t hi0, lo0, hi1, lo1;
            split2(v0, v1, hi0, lo0);
            split2(v2, v3, hi1, lo1);
            *(uint32_t*)&Oh[(size_t)r0 * QKV_COLS + cc]       = hi0;
            *(uint32_t*)&Oh[(size_t)(r0 + 8) * QKV_COLS + cc] = hi1;
            if (which == 0) {
                *(uint32_t*)&g_Ql[(size_t)r0 * QKV_COLS + cc]       = lo0;
                *(uint32_t*)&g_Ql[(size_t)(r0 + 8) * QKV_COLS + cc] = lo1;
            }
        }
    }

    if (which == 1) {
        float s0 = ssA[0], s1 = ssB[0], s2 = ssA[1], s3 = ssB[1];
        #pragma unroll
        for (int off = 1; off <= 2; off <<= 1) {
            s0 += __shfl_xor_sync(0xffffffffu, s0, off);
            s1 += __shfl_xor_sync(0xffffffffu, s1, off);
            s2 += __shfl_xor_sync(0xffffffffu, s2, off);
            s3 += __shfl_xor_sync(0xffffffffu, s3, off);
        }
        float mx = fmaxf(fmaxf(s0, s1), fmaxf(s2, s3));
        #pragma unroll
        for (int off = 4; off <= 16; off <<= 1)
            mx = fmaxf(mx, __shfl_xor_sync(0xffffffffu, mx, off));
        if (lane == 0) {
            int bh = (row0 >> 10) * NUM_HEADS + ((col0 + 64 * warp_n) >> 6);
            atomicMax((unsigned int*)&g_kmax[bh], __float_as_uint(mx));
        }
    }
}

// ---------------------------------------------------------------------------
// Kernel 2: fp16 flash attention.  QK 2-pass, PV single-pass with rounded-P
// consistency (l accumulated from the SAME rounded p used in the MMA).
// BR=64, 4 warps, 3 CTAs/SM, cp.async double-buffered K/V, packed adjacency.
// ---------------------------------------------------------------------------
#define TSTR 72
#define KTILE_E (64 * TSTR)

__global__ __launch_bounds__(128, 3)
void attn_mma_kernel(float* __restrict__ out)
{
    extern __shared__ __half sm[];
    __half* sQh = sm;                    // [64][TSTR]
    __half* sQl = sQh + KTILE_E;
    __half* sK0 = sQl + KTILE_E;         // K/V double buffers
    __half* sK1 = sK0 + KTILE_E;
    __half* sV0 = sK1 + KTILE_E;
    __half* sV1 = sV0 + KTILE_E;
    float* sM = (float*)(sV1 + KTILE_E); // [64]

    const int b  = blockIdx.z;
    const int hd = blockIdx.y;
    const int q0 = blockIdx.x * 64;
    const int tid  = threadIdx.x;
    const int w    = tid >> 5;
    const int lane = tid & 31;
    const int g  = lane >> 2;
    const int t4 = lane & 3;

    const size_t bN  = (size_t)b * SEQ;
    const int hdo = hd * OUT_DIM;

    const uint32_t kbase[2] = { smem_u32(sK0), smem_u32(sK1) };
    const uint32_t vbase[2] = { smem_u32(sV0), smem_u32(sV1) };

    auto stage_kv = [&](int t, int buf) {
        const int m0 = t * 64;
        #pragma unroll
        for (int it = 0; it < 4; it++) {
            int lin = it * 128 + tid;
            int r  = lin >> 3;
            int c8 = (lin & 7) * 8;
            size_t gofs = (bN + m0 + r) * QKV_COLS + hdo + c8;
            uint32_t so = (uint32_t)(r * TSTR + c8) * 2;
            cp16(kbase[buf] + so, &g_Kh[gofs]);
            cp16(vbase[buf] + so, &g_Vh[gofs]);
        }
        CP_COMMIT();
    };

    #pragma unroll
    for (int it = 0; it < 4; it++) {
        int lin = it * 128 + tid;
        int r  = lin >> 3;
        int c8 = (lin & 7) * 8;
        *(uint4*)&sQh[r * TSTR + c8] =
            *(const uint4*)&g_Qh[(bN + q0 + r) * QKV_COLS + hdo + c8];
        *(uint4*)&sQl[r * TSTR + c8] =
            *(const uint4*)&g_Ql[(bN + q0 + r) * QKV_COLS + hdo + c8];
    }
    stage_kv(0, 0);
    __syncthreads();

    const float kmax2 = g_kmax[b * NUM_HEADS + hd];
    if (tid < 64) {
        float ss = 0.f;
        #pragma unroll
        for (int c = 0; c < 8; c++) {
            uint4 uh = *(const uint4*)&sQh[tid * TSTR + c * 8];
            uint4 ul = *(const uint4*)&sQl[tid * TSTR + c * 8];
            const uint32_t* ph = (const uint32_t*)&uh;
            const uint32_t* pl = (const uint32_t*)&ul;
            #pragma unroll
            for (int q = 0; q < 4; q++) {
                float2 fh = hf2f(ph[q]), fl = hf2f(pl[q]);
                float a = fh.x + fl.x, c2 = fh.y + fl.y;
                ss = fmaf(a, a, ss); ss = fmaf(c2, c2, ss);
            }
        }
        sM[tid] = sqrtf(ss * kmax2);
    }
    __syncthreads();

    const uint32_t qbase_h = smem_u32(sQh);
    const uint32_t qbase_l = smem_u32(sQl);
    uint32_t qh[4][4], ql[4][4];
    {
        int row = 16 * w + (lane & 7) + 8 * ((lane >> 3) & 1);
        int dof = 8 * (lane >> 4);
        #pragma unroll
        for (int kt = 0; kt < 4; kt++) {
            uint32_t off = (uint32_t)(row * TSTR + 16 * kt + dof) * 2;
            ldsm_x4(qh[kt], qbase_h + off);
            ldsm_x4(ql[kt], qbase_l + off);
        }
    }
    const float mg = sM[16 * w + g];
    const float m2 = sM[16 * w + g + 8];

    const int r1 = q0 + 16 * w + g;
    const unsigned long long* abits0 = &g_adjbits[(size_t)r1 * 16];
    const unsigned long long* abits1 = &g_adjbits[(size_t)(r1 + 8) * 16];

    float o[8][4] = {};
    float lg = 0.f, l2 = 0.f;

    for (int t = 0; t < SEQ / 64; t++) {
        const unsigned long long m0s = abits0[t] >> (2 * t4);
        const unsigned long long m1s = abits1[t] >> (2 * t4);

        CP_WAIT0();
        __syncthreads();
        if (t < SEQ / 64 - 1) stage_kv(t + 1, (t + 1) & 1);

        const uint32_t kb = kbase[t & 1];
        const uint32_t vb = vbase[t & 1];

        // ---- QK^T (2-pass) + mask + exp + pack; rounded-P consistency ----
        uint32_t ph[4][4];
        const int krow = (lane & 7);
        const int kdof = 8 * (lane >> 3);
        #pragma unroll
        for (int kt = 0; kt < 4; kt++) {
            uint32_t b0[8], b1[8];
            uint32_t roff0 = (uint32_t)((16 * kt + krow) * TSTR + kdof) * 2;
            uint32_t roff1 = (uint32_t)((16 * kt + 8 + krow) * TSTR + kdof) * 2;
            ldsm_x4(b0 + 0, kb + roff0);
            ldsm_x4(b0 + 4, kb + roff0 + 64);
            ldsm_x4(b1 + 0, kb + roff1);
            ldsm_x4(b1 + 4, kb + roff1 + 64);
            float d0[4] = {}, d1[4] = {};
            #pragma unroll
            for (int kc = 0; kc < 4; kc++) {
                int hi2 = kc >> 1, oo = (kc & 1) * 2;
                mma16816(d0, qh[kc], b0[4 * hi2 + oo], b0[4 * hi2 + oo + 1]);
                mma16816(d1, qh[kc], b1[4 * hi2 + oo], b1[4 * hi2 + oo + 1]);
            }
            #pragma unroll
            for (int kc = 0; kc < 4; kc++) {
                int hi2 = kc >> 1, oo = (kc & 1) * 2;
                mma16816(d0, ql[kc], b0[4 * hi2 + oo], b0[4 * hi2 + oo + 1]);
                mma16816(d1, ql[kc], b1[4 * hi2 + oo], b1[4 * hi2 + oo + 1]);
            }
            unsigned b00 = (unsigned)(m0s >> (16 * kt)) & 3u;
            unsigned b01 = (unsigned)(m1s >> (16 * kt)) & 3u;
            unsigned b10 = (unsigned)(m0s >> (16 * kt + 8)) & 3u;
            unsigned b11 = (unsigned)(m1s >> (16 * kt + 8)) & 3u;
            float p00 = (b00 & 1) ? ex2(d0[0] - mg) : 0.f;
            float p01 = (b00 & 2) ? ex2(d0[1] - mg) : 0.f;
            float p02 = (b01 & 1) ? ex2(d0[2] - m2) : 0.f;
            float p03 = (b01 & 2) ? ex2(d0[3] - m2) : 0.f;
            float p10 = (b10 & 1) ? ex2(d1[0] - mg) : 0.f;
            float p11 = (b10 & 2) ? ex2(d1[1] - mg) : 0.f;
            float p12 = (b11 & 1) ? ex2(d1[2] - m2) : 0.f;
            float p13 = (b11 & 2) ? ex2(d1[3] - m2) : 0.f;
            // pack to fp16 and accumulate l from the ROUNDED values
            ph[kt][0] = pack_hf2(p00, p01);
            ph[kt][1] = pack_hf2(p02, p03);
            ph[kt][2] = pack_hf2(p10, p11);
            ph[kt][3] = pack_hf2(p12, p13);
            float2 u0 = hf2f(ph[kt][0]);
            float2 u1 = hf2f(ph[kt][1]);
            float2 u2 = hf2f(ph[kt][2]);
            float2 u3 = hf2f(ph[kt][3]);
            lg += (u0.x + u0.y) + (u2.x + u2.y);
            l2 += (u1.x + u1.y) + (u3.x + u3.y);
        }

        // ---- PV: single pass (rounded P x v_hi), j-pairs interleaved ----
        const int vrow = 8 * (lane >> 3) + (lane & 7);
        const uint32_t vr0  = (uint32_t)(vrow * TSTR) * 2;
        const uint32_t vr32 = (uint32_t)((vrow + 32) * TSTR) * 2;
        #pragma unroll
        for (int jp = 0; jp < 4; jp++) {
            const int j0 = 2 * jp, j1 = j0 + 1;
            uint32_t b0[8], b1[8];
            uint32_t c0 = (uint32_t)(8 * j0) * 2;
            uint32_t c1 = (uint32_t)(8 * j1) * 2;
            ldsm_x4_t(b0 + 0, vb + vr0 + c0);
            ldsm_x4_t(b0 + 4, vb + vr32 + c0);
            ldsm_x4_t(b1 + 0, vb + vr0 + c1);
            ldsm_x4_t(b1 + 4, vb + vr32 + c1);
            #pragma unroll
            for (int kt = 0; kt < 4; kt++) {
                int hi2 = kt >> 1, oo = (kt & 1) * 2;
                mma16816(o[j0], ph[kt], b0[4 * hi2 + oo], b0[4 * hi2 + oo + 1]);
                mma16816(o[j1], ph[kt], b1[4 * hi2 + oo], b1[4 * hi2 + oo + 1]);
            }
        }
    }

    lg += __shfl_xor_sync(0xffffffffu, lg, 1);
    lg += __shfl_xor_sync(0xffffffffu, lg, 2);
    l2 += __shfl_xor_sync(0xffffffffu, l2, 1);
    l2 += __shfl_xor_sync(0xffffffffu, l2, 2);
    const float invg = 1.0f / lg;
    const float inv2 = 1.0f / l2;

    #pragma unroll
    for (int j = 0; j < 8; j++) {
        int cc = hdo + 8 * j + 2 * t4;
        *(float2*)&out[(bN + r1) * QKV_COLS + cc] =
            make_float2(o[j][0] * invg, o[j][1] * invg);
        *(float2*)&out[(bN + r1 + 8) * QKV_COLS + cc] =
            make_float2(o[j][2] * inv2, o[j][3] * inv2);
    }
}

// ---------------------------------------------------------------------------
// Launch
// ---------------------------------------------------------------------------
extern "C" void kernel_launch(void* const* d_in, const int* in_sizes, int n_in,
                              void* d_out, int out_size)
{
    const int*   adj = (const int*)  d_in[0];
    const float* h   = (const float*)d_in[1];
    const float* Wq  = (const float*)d_in[2];
    const float* bq  = (const float*)d_in[3];
    const float* Wk  = (const float*)d_in[4];
    const float* bk  = (const float*)d_in[5];
    const float* Wv  = (const float*)d_in[6];
    const float* bv  = (const float*)d_in[7];
    float* out = (float*)d_out;

    qkv_mma_kernel<<<dim3(QKV_COLS / 128, ROWS / 128, 4), 256>>>(
        h, Wq, Wk, Wv, bq, bk, bv, adj);

    const int smem_bytes = 6 * KTILE_E * 2 + 64 * 4;   // 55,552 B
    static bool attr_set = false;
    if (!attr_set) {
        cudaFuncSetAttribute(attn_mma_kernel,
                             cudaFuncAttributeMaxDynamicSharedMemorySize, smem_bytes);
        attr_set = true;
    }
    attn_mma_kernel<<<dim3(SEQ / 64, NUM_HEADS, BATCH), 128, smem_bytes>>>(out);
}